// round 1
// baseline (speedup 1.0000x reference)
#include <cuda_runtime.h>

#define D     1024
#define NROW  4096
#define BM    128
#define BN    128
#define BK    16
#define PAD   4
#define LDA   (BM + PAD)

__device__ float g_nx[NROW];
__device__ float g_ny[NROW];

// One block per row (first NROW blocks -> x, next NROW -> y). 256 threads,
// each reads one float4 (1024 floats/row), reduce sum of squares, sqrt.
__global__ __launch_bounds__(256) void norm_kernel(const float* __restrict__ x,
                                                   const float* __restrict__ y) {
    const int row = blockIdx.x;
    const float* p = (row < NROW) ? (x + (size_t)row * D)
                                  : (y + (size_t)(row - NROW) * D);
    float4 v = reinterpret_cast<const float4*>(p)[threadIdx.x];
    float s = v.x * v.x + v.y * v.y + v.z * v.z + v.w * v.w;
    #pragma unroll
    for (int o = 16; o > 0; o >>= 1) s += __shfl_down_sync(0xffffffffu, s, o);
    __shared__ float ws[8];
    const int lane = threadIdx.x & 31, w = threadIdx.x >> 5;
    if (lane == 0) ws[w] = s;
    __syncthreads();
    if (threadIdx.x == 0) {
        float t = 0.f;
        #pragma unroll
        for (int i = 0; i < 8; i++) t += ws[i];
        const float n = sqrtf(t);
        if (row < NROW) g_nx[row] = n;
        else            g_ny[row - NROW] = n;
    }
}

// O[i][j] = (sum_k X[i][k]*Y[j][k]) / max(nx[i]*ny[j], 1e-8) / 0.05
// 128x128 CTA tile, BK=16, 256 threads, 8x8 per-thread microtile.
// Both operands are K-contiguous (A * B^T), so the smem tiles are stored
// transposed ([BK][BM]) for broadcast/vector LDS in the inner loop.
__global__ __launch_bounds__(256, 2) void cosgemm_kernel(
    const float* __restrict__ X, const float* __restrict__ Y,
    float* __restrict__ O) {
    __shared__ float As[BK][LDA];
    __shared__ float Bs[BK][LDA];

    const int tid = threadIdx.x;
    const int tx  = tid & 15;        // output column group
    const int ty  = tid >> 4;        // output row group
    const int lr  = tid >> 2;        // 0..63  : load row within half-tile
    const int lc  = (tid & 3) << 2;  // 0,4,8,12: load col (float4)

    const float* Xg = X + (size_t)(blockIdx.y * BM + lr) * D + lc;
    const float* Yg = Y + (size_t)(blockIdx.x * BN + lr) * D + lc;

    float acc[8][8];
    #pragma unroll
    for (int i = 0; i < 8; i++)
        #pragma unroll
        for (int j = 0; j < 8; j++) acc[i][j] = 0.f;

    for (int k0 = 0; k0 < D; k0 += BK) {
        #pragma unroll
        for (int r = 0; r < 2; r++) {
            const float4 va = *reinterpret_cast<const float4*>(Xg + (size_t)(r * 64) * D + k0);
            const float4 vb = *reinterpret_cast<const float4*>(Yg + (size_t)(r * 64) * D + k0);
            const int rr = lr + r * 64;
            As[lc + 0][rr] = va.x; As[lc + 1][rr] = va.y;
            As[lc + 2][rr] = va.z; As[lc + 3][rr] = va.w;
            Bs[lc + 0][rr] = vb.x; Bs[lc + 1][rr] = vb.y;
            Bs[lc + 2][rr] = vb.z; Bs[lc + 3][rr] = vb.w;
        }
        __syncthreads();

        #pragma unroll
        for (int k = 0; k < BK; k++) {
            float ra[8], rb[8];
            *reinterpret_cast<float4*>(&ra[0]) = *reinterpret_cast<const float4*>(&As[k][ty * 8]);
            *reinterpret_cast<float4*>(&ra[4]) = *reinterpret_cast<const float4*>(&As[k][ty * 8 + 4]);
            *reinterpret_cast<float4*>(&rb[0]) = *reinterpret_cast<const float4*>(&Bs[k][tx * 8]);
            *reinterpret_cast<float4*>(&rb[4]) = *reinterpret_cast<const float4*>(&Bs[k][tx * 8 + 4]);
            #pragma unroll
            for (int i = 0; i < 8; i++)
                #pragma unroll
                for (int j = 0; j < 8; j++)
                    acc[i][j] = fmaf(ra[i], rb[j], acc[i][j]);
        }
        __syncthreads();
    }

    // Fused cosine epilogue
    const int orow = blockIdx.y * BM + ty * 8;
    const int ocol = blockIdx.x * BN + tx * 8;
    float rn[8], cn[8];
    #pragma unroll
    for (int i = 0; i < 8; i++) rn[i] = g_nx[orow + i];
    #pragma unroll
    for (int j = 0; j < 8; j++) cn[j] = g_ny[ocol + j];

    #pragma unroll
    for (int i = 0; i < 8; i++) {
        float out[8];
        #pragma unroll
        for (int j = 0; j < 8; j++) {
            const float den = fmaxf(rn[i] * cn[j], 1e-8f);
            out[j] = acc[i][j] / den / 0.05f;
        }
        float* dst = O + (size_t)(orow + i) * NROW + ocol;
        *reinterpret_cast<float4*>(dst)     = make_float4(out[0], out[1], out[2], out[3]);
        *reinterpret_cast<float4*>(dst + 4) = make_float4(out[4], out[5], out[6], out[7]);
    }
}

extern "C" void kernel_launch(void* const* d_in, const int* in_sizes, int n_in,
                              void* d_out, int out_size) {
    const float* x = (const float*)d_in[0];
    const float* y = (const float*)d_in[1];
    float* o = (float*)d_out;
    (void)in_sizes; (void)n_in; (void)out_size;

    norm_kernel<<<2 * NROW, 256>>>(x, y);
    dim3 grid(NROW / BN, NROW / BM);
    cosgemm_kernel<<<grid, 256>>>(x, y, o);
}

// round 3
// speedup vs baseline: 1.3730x; 1.3730x over previous
#include <cuda_runtime.h>
#include <cuda_bf16.h>
#include <cstdint>

#define D       1024
#define NROW    4096
#define BM      128
#define BN      128
#define BK      32
#define NCHUNK  (D / BK)          // 32
#define ROWB    80                // 32 bf16 (64B) + 16B pad -> conflict-free ldmatrix
#define ARRB    (128 * ROWB)      // 10240 B per operand array per stage
#define STAGEB  (4 * ARRB)        // Ahi, Alo, Bhi, Blo = 40960 B
#define NSTAGE  3
#define SMEM_TOTAL (NSTAGE * STAGEB)   // 122880 B

// ---- scratch (allocation-guard-safe __device__ globals) ----
__device__ __align__(256) __nv_bfloat16 g_xh[NROW * D];
__device__ __align__(256) __nv_bfloat16 g_xl[NROW * D];
__device__ __align__(256) __nv_bfloat16 g_yh[NROW * D];
__device__ __align__(256) __nv_bfloat16 g_yl[NROW * D];
__device__ __align__(16)  float g_rnx[NROW];   // 20 / ||x_i||  (temp folded)
__device__ __align__(16)  float g_rny[NROW];   // 1 / ||y_j||

// ---- helpers ----
__device__ __forceinline__ uint32_t smem_u32(const void* p) {
    uint32_t a;
    asm("{ .reg .u64 t; cvta.to.shared.u64 t, %1; cvt.u32.u64 %0, t; }" : "=r"(a) : "l"(p));
    return a;
}
__device__ __forceinline__ void cp16(uint32_t s, const void* g) {
    asm volatile("cp.async.cg.shared.global [%0], [%1], 16;" :: "r"(s), "l"(g));
}
#define CP_COMMIT() asm volatile("cp.async.commit_group;" ::: "memory")
template <int N>
__device__ __forceinline__ void cp_wait() {
    asm volatile("cp.async.wait_group %0;" :: "n"(N) : "memory");
}
__device__ __forceinline__ void ldsm4(uint32_t* r, uint32_t addr) {
    asm volatile("ldmatrix.sync.aligned.m8n8.x4.shared.b16 {%0,%1,%2,%3}, [%4];"
                 : "=r"(r[0]), "=r"(r[1]), "=r"(r[2]), "=r"(r[3]) : "r"(addr));
}
__device__ __forceinline__ void mma_bf16(float* d, const uint32_t* a, const uint32_t* b) {
    asm volatile(
        "mma.sync.aligned.m16n8k16.row.col.f32.bf16.bf16.f32 "
        "{%0,%1,%2,%3}, {%4,%5,%6,%7}, {%8,%9}, {%0,%1,%2,%3};"
        : "+f"(d[0]), "+f"(d[1]), "+f"(d[2]), "+f"(d[3])
        : "r"(a[0]), "r"(a[1]), "r"(a[2]), "r"(a[3]), "r"(b[0]), "r"(b[1]));
}

// ---- norm kernel: reciprocal norms, temperature folded into X side ----
__global__ __launch_bounds__(256) void norm_kernel(const float* __restrict__ x,
                                                   const float* __restrict__ y) {
    const int row = blockIdx.x;
    const float* p = (row < NROW) ? (x + (size_t)row * D)
                                  : (y + (size_t)(row - NROW) * D);
    float4 v = reinterpret_cast<const float4*>(p)[threadIdx.x];
    float s = v.x * v.x + v.y * v.y + v.z * v.z + v.w * v.w;
    #pragma unroll
    for (int o = 16; o > 0; o >>= 1) s += __shfl_down_sync(0xffffffffu, s, o);
    __shared__ float ws[8];
    const int lane = threadIdx.x & 31, w = threadIdx.x >> 5;
    if (lane == 0) ws[w] = s;
    __syncthreads();
    if (threadIdx.x == 0) {
        float t = 0.f;
        #pragma unroll
        for (int i = 0; i < 8; i++) t += ws[i];
        const float n = sqrtf(t);
        if (row < NROW) g_rnx[row] = 20.0f / n;
        else            g_rny[row - NROW] = 1.0f / n;
    }
}

// ---- split kernel: fp32 -> bf16 hi + bf16 residual lo ----
__global__ __launch_bounds__(256) void split_kernel(const float* __restrict__ x,
                                                    const float* __restrict__ y) {
    const int idx = blockIdx.x * 256 + threadIdx.x;   // float4 index
    const bool isy = (blockIdx.y != 0);
    const float4 v = reinterpret_cast<const float4*>(isy ? y : x)[idx];
    float f[4] = {v.x, v.y, v.z, v.w};
    __nv_bfloat16 h[4], l[4];
    #pragma unroll
    for (int i = 0; i < 4; i++) {
        h[i] = __float2bfloat16_rn(f[i]);
        l[i] = __float2bfloat16_rn(f[i] - __bfloat162float(h[i]));
    }
    uint2 hv, lv;
    hv.x = ((uint32_t)__bfloat16_as_ushort(h[0])) | ((uint32_t)__bfloat16_as_ushort(h[1]) << 16);
    hv.y = ((uint32_t)__bfloat16_as_ushort(h[2])) | ((uint32_t)__bfloat16_as_ushort(h[3]) << 16);
    lv.x = ((uint32_t)__bfloat16_as_ushort(l[0])) | ((uint32_t)__bfloat16_as_ushort(l[1]) << 16);
    lv.y = ((uint32_t)__bfloat16_as_ushort(l[2])) | ((uint32_t)__bfloat16_as_ushort(l[3]) << 16);
    reinterpret_cast<uint2*>(isy ? g_yh : g_xh)[idx] = hv;
    reinterpret_cast<uint2*>(isy ? g_yl : g_xl)[idx] = lv;
}

// ---- main GEMM: mma.sync bf16, 3-product split, fused cosine epilogue ----
__global__ __launch_bounds__(256) void cosgemm_kernel(float* __restrict__ O) {
    extern __shared__ char smem[];
    const uint32_t sb = smem_u32(smem);
    const int tid = threadIdx.x;
    const int w = tid >> 5, lane = tid & 31;
    const int wm = w >> 2, wn = w & 3;      // 2 x 4 warp grid, warp tile 64x32
    const int row0 = blockIdx.y * BM;
    const int col0 = blockIdx.x * BN;

    // cp.async slots: 512 16B-slots per array, 2 per thread per array
    const int s0 = tid, s1 = tid + 256;
    const uint32_t so0 = (uint32_t)((s0 >> 2) * ROWB + (s0 & 3) * 16);
    const uint32_t so1 = (uint32_t)((s1 >> 2) * ROWB + (s1 & 3) * 16);
    const size_t gA0 = (size_t)(row0 + (s0 >> 2)) * D + (s0 & 3) * 8;
    const size_t gA1 = (size_t)(row0 + (s1 >> 2)) * D + (s1 & 3) * 8;
    const size_t gB0 = (size_t)(col0 + (s0 >> 2)) * D + (s0 & 3) * 8;
    const size_t gB1 = (size_t)(col0 + (s1 >> 2)) * D + (s1 & 3) * 8;

    auto load_chunk = [&](int i) {
        const int k0 = i * BK;
        const uint32_t st = sb + (uint32_t)(i % NSTAGE) * STAGEB;
        cp16(st + so0,            g_xh + gA0 + k0);
        cp16(st + so1,            g_xh + gA1 + k0);
        cp16(st + ARRB + so0,     g_xl + gA0 + k0);
        cp16(st + ARRB + so1,     g_xl + gA1 + k0);
        cp16(st + 2 * ARRB + so0, g_yh + gB0 + k0);
        cp16(st + 2 * ARRB + so1, g_yh + gB1 + k0);
        cp16(st + 3 * ARRB + so0, g_yl + gB0 + k0);
        cp16(st + 3 * ARRB + so1, g_yl + gB1 + k0);
        CP_COMMIT();
    };

    // ldmatrix per-lane base offsets
    // A (16x16 tile): row = lane%16, byte-col = (lane/16)*16
    const uint32_t aoff = (uint32_t)((wm * 64 + (lane & 15)) * ROWB + (lane >> 4) * 16);
    // B (two n8k16 tiles): n = lane%8 + (lane/16)*8, byte-k = ((lane>>3)&1)*16
    const uint32_t boff = (uint32_t)((wn * 32 + (lane & 7) + ((lane >> 4) << 3)) * ROWB
                                     + ((lane >> 3) & 1) * 16);

    float acc[4][4][4];
    #pragma unroll
    for (int mi = 0; mi < 4; mi++)
        #pragma unroll
        for (int ni = 0; ni < 4; ni++)
            #pragma unroll
            for (int r = 0; r < 4; r++) acc[mi][ni][r] = 0.f;

    load_chunk(0);
    load_chunk(1);

    for (int i = 0; i < NCHUNK; i++) {
        if (i + 2 < NCHUNK)      { load_chunk(i + 2); cp_wait<2>(); }
        else if (i == NCHUNK - 2) cp_wait<1>();
        else                      cp_wait<0>();
        __syncthreads();

        const uint32_t st = sb + (uint32_t)(i % NSTAGE) * STAGEB;
        const uint32_t a_hi = st + aoff;
        const uint32_t a_lo = st + ARRB + aoff;
        const uint32_t b_hi = st + 2 * ARRB + boff;
        const uint32_t b_lo = st + 3 * ARRB + boff;

        #pragma unroll
        for (int s = 0; s < 2; s++) {
            uint32_t ah[4][4], al[4][4], bh[2][4], bl[2][4];
            #pragma unroll
            for (int mi = 0; mi < 4; mi++) {
                ldsm4(ah[mi], a_hi + (uint32_t)(mi * 16 * ROWB + s * 32));
                ldsm4(al[mi], a_lo + (uint32_t)(mi * 16 * ROWB + s * 32));
            }
            #pragma unroll
            for (int np = 0; np < 2; np++) {
                ldsm4(bh[np], b_hi + (uint32_t)(np * 16 * ROWB + s * 32));
                ldsm4(bl[np], b_lo + (uint32_t)(np * 16 * ROWB + s * 32));
            }
            #pragma unroll
            for (int mi = 0; mi < 4; mi++) {
                #pragma unroll
                for (int ni = 0; ni < 4; ni++) {
                    const uint32_t* bhp = &bh[ni >> 1][(ni & 1) * 2];
                    const uint32_t* blp = &bl[ni >> 1][(ni & 1) * 2];
                    mma_bf16(acc[mi][ni], ah[mi], bhp);
                    mma_bf16(acc[mi][ni], ah[mi], blp);
                    mma_bf16(acc[mi][ni], al[mi], bhp);
                }
            }
        }
        __syncthreads();
    }

    // fused cosine epilogue
    const int rbase = row0 + wm * 64 + (lane >> 2);
    const int cbase = col0 + wn * 32 + (lane & 3) * 2;
    #pragma unroll
    for (int mi = 0; mi < 4; mi++) {
        const int r = rbase + mi * 16;
        const float n0 = g_rnx[r];
        const float n1 = g_rnx[r + 8];
        #pragma unroll
        for (int ni = 0; ni < 4; ni++) {
            const int c = cbase + ni * 8;
            const float2 ry = *reinterpret_cast<const float2*>(g_rny + c);
            float2 o0, o1;
            o0.x = acc[mi][ni][0] * n0 * ry.x;
            o0.y = acc[mi][ni][1] * n0 * ry.y;
            o1.x = acc[mi][ni][2] * n1 * ry.x;
            o1.y = acc[mi][ni][3] * n1 * ry.y;
            *reinterpret_cast<float2*>(O + (size_t)r * NROW + c)       = o0;
            *reinterpret_cast<float2*>(O + (size_t)(r + 8) * NROW + c) = o1;
        }
    }
}

extern "C" void kernel_launch(void* const* d_in, const int* in_sizes, int n_in,
                              void* d_out, int out_size) {
    const float* x = (const float*)d_in[0];
    const float* y = (const float*)d_in[1];
    float* o = (float*)d_out;
    (void)in_sizes; (void)n_in; (void)out_size;

    norm_kernel<<<2 * NROW, 256>>>(x, y);
    split_kernel<<<dim3(NROW * D / 1024, 2), 256>>>(x, y);

    cudaFuncSetAttribute(cosgemm_kernel, cudaFuncAttributeMaxDynamicSharedMemorySize, SMEM_TOTAL);
    cosgemm_kernel<<<dim3(NROW / BN, NROW / BM), 256, SMEM_TOTAL>>>(o);
}

// round 4
// speedup vs baseline: 7.4548x; 5.4297x over previous
#include <cuda_runtime.h>
#include <cuda_fp16.h>
#include <cstdint>

#define D       1024
#define NROW    4096
#define BM      128
#define BN      128
#define BK      64                 // 64 fp16 = 128 B per row-chunk
#define NCHUNK  (D / BK)           // 16
#define ROWB    128                // bytes per smem row (XOR-swizzled, no pad)
#define ARRB    (128 * ROWB)       // 16 KB per operand per stage
#define STAGEB  (2 * ARRB)         // 32 KB
#define NSTAGE  3
#define SMEM_TOTAL (NSTAGE * STAGEB)   // 98304 B -> 2 CTAs/SM

// ---- scratch (allocation-guard-safe __device__ globals) ----
__device__ __align__(256) __half g_xh[NROW * D];
__device__ __align__(256) __half g_yh[NROW * D];
__device__ __align__(16)  float  g_rnx[NROW];   // 20 / ||x_i||  (temp folded)
__device__ __align__(16)  float  g_rny[NROW];   // 1 / ||y_j||

// ---- helpers ----
__device__ __forceinline__ uint32_t smem_u32(const void* p) {
    uint32_t a;
    asm("{ .reg .u64 t; cvta.to.shared.u64 t, %1; cvt.u32.u64 %0, t; }" : "=r"(a) : "l"(p));
    return a;
}
__device__ __forceinline__ void cp16(uint32_t s, const void* g) {
    asm volatile("cp.async.cg.shared.global [%0], [%1], 16;" :: "r"(s), "l"(g));
}
#define CP_COMMIT() asm volatile("cp.async.commit_group;" ::: "memory")
template <int N>
__device__ __forceinline__ void cp_wait() {
    asm volatile("cp.async.wait_group %0;" :: "n"(N) : "memory");
}
__device__ __forceinline__ void ldsm4(uint32_t* r, uint32_t addr) {
    asm volatile("ldmatrix.sync.aligned.m8n8.x4.shared.b16 {%0,%1,%2,%3}, [%4];"
                 : "=r"(r[0]), "=r"(r[1]), "=r"(r[2]), "=r"(r[3]) : "r"(addr));
}
__device__ __forceinline__ void mma_fp16(float* d, const uint32_t* a, const uint32_t* b) {
    asm volatile(
        "mma.sync.aligned.m16n8k16.row.col.f32.f16.f16.f32 "
        "{%0,%1,%2,%3}, {%4,%5,%6,%7}, {%8,%9}, {%0,%1,%2,%3};"
        : "+f"(d[0]), "+f"(d[1]), "+f"(d[2]), "+f"(d[3])
        : "r"(a[0]), "r"(a[1]), "r"(a[2]), "r"(a[3]), "r"(b[0]), "r"(b[1]));
}

// ---- fused norm + fp16-convert prologue: one read pass over x and y ----
// block = one row. Computes reciprocal norm (temp folded into x side) and
// writes the fp16 copy used by the GEMM.
__global__ __launch_bounds__(256) void prep_kernel(const float* __restrict__ x,
                                                   const float* __restrict__ y) {
    const int row = blockIdx.x;
    const bool isy = (row >= NROW);
    const int r = isy ? row - NROW : row;
    const float* p = (isy ? y : x) + (size_t)r * D;
    const float4 v = reinterpret_cast<const float4*>(p)[threadIdx.x];

    // fp16 copy
    __half2 h0 = __floats2half2_rn(v.x, v.y);
    __half2 h1 = __floats2half2_rn(v.z, v.w);
    uint2 hv;
    hv.x = *reinterpret_cast<uint32_t*>(&h0);
    hv.y = *reinterpret_cast<uint32_t*>(&h1);
    reinterpret_cast<uint2*>((isy ? g_yh : g_xh) + (size_t)r * D)[threadIdx.x] = hv;

    // norm reduction
    float s = v.x * v.x + v.y * v.y + v.z * v.z + v.w * v.w;
    #pragma unroll
    for (int o = 16; o > 0; o >>= 1) s += __shfl_down_sync(0xffffffffu, s, o);
    __shared__ float ws[8];
    const int lane = threadIdx.x & 31, w = threadIdx.x >> 5;
    if (lane == 0) ws[w] = s;
    __syncthreads();
    if (threadIdx.x == 0) {
        float t = 0.f;
        #pragma unroll
        for (int i = 0; i < 8; i++) t += ws[i];
        const float n = sqrtf(t);
        if (isy) g_rny[r] = 1.0f / n;
        else     g_rnx[r] = 20.0f / n;
    }
}

// ---- main GEMM: single-pass fp16 mma.sync, fused cosine epilogue ----
__global__ __launch_bounds__(256, 2) void cosgemm_kernel(float* __restrict__ O) {
    extern __shared__ char smem[];
    const uint32_t sb = smem_u32(smem);
    const int tid = threadIdx.x;
    const int w = tid >> 5, lane = tid & 31;
    const int wm = w >> 2, wn = w & 3;      // 2 x 4 warp grid, warp tile 64x32
    const int row0 = blockIdx.y * BM;
    const int col0 = blockIdx.x * BN;
    const int lx = lane & 7;                // per-lane swizzle key

    // cp.async: 8 atoms (16B) per 128B row; id -> (row, atom), atom XOR row&7
    uint32_t soff[4]; size_t gA[4], gB[4];
    #pragma unroll
    for (int k = 0; k < 4; k++) {
        const int id = k * 256 + tid;
        const int r = id >> 3, c = id & 7;
        soff[k] = (uint32_t)(r * ROWB + ((c ^ (r & 7)) * 16));
        gA[k] = (size_t)(row0 + r) * D + c * 8;
        gB[k] = (size_t)(col0 + r) * D + c * 8;
    }

    auto load_chunk = [&](int i) {
        const int k0 = i * BK;
        const uint32_t st = sb + (uint32_t)(i % NSTAGE) * STAGEB;
        #pragma unroll
        for (int k = 0; k < 4; k++) cp16(st + soff[k],        g_xh + gA[k] + k0);
        #pragma unroll
        for (int k = 0; k < 4; k++) cp16(st + ARRB + soff[k], g_yh + gB[k] + k0);
        CP_COMMIT();
    };

    // ldmatrix per-lane row-base offsets (col atom computed per k-step)
    const uint32_t arow = (uint32_t)((wm * 64 + (lane & 15)) * ROWB);
    const uint32_t brow = (uint32_t)((wn * 32 + (lane & 7) + ((lane >> 4) << 3)) * ROWB);
    const int acat = (lane >> 4);        // A: 0/1 -> k-atom within step
    const int bcat = ((lane >> 3) & 1);  // B: 0/1

    float acc[4][4][4];
    #pragma unroll
    for (int mi = 0; mi < 4; mi++)
        #pragma unroll
        for (int ni = 0; ni < 4; ni++)
            #pragma unroll
            for (int r = 0; r < 4; r++) acc[mi][ni][r] = 0.f;

    load_chunk(0);
    load_chunk(1);

    for (int i = 0; i < NCHUNK; i++) {
        if (i + 2 < NCHUNK)      { load_chunk(i + 2); cp_wait<2>(); }
        else if (i == NCHUNK - 2) cp_wait<1>();
        else                      cp_wait<0>();
        __syncthreads();

        const uint32_t st = sb + (uint32_t)(i % NSTAGE) * STAGEB;
        const uint32_t stB = st + ARRB;

        #pragma unroll
        for (int s = 0; s < 4; s++) {    // 4 k16 steps per BK=64 chunk
            const uint32_t aco = (uint32_t)(((s * 2 + acat) ^ lx) * 16);
            const uint32_t bco = (uint32_t)(((s * 2 + bcat) ^ lx) * 16);
            uint32_t a[4][4], b[2][4];
            #pragma unroll
            for (int mi = 0; mi < 4; mi++)
                ldsm4(a[mi], st + arow + (uint32_t)(mi * 16 * ROWB) + aco);
            #pragma unroll
            for (int np = 0; np < 2; np++)
                ldsm4(b[np], stB + brow + (uint32_t)(np * 16 * ROWB) + bco);
            #pragma unroll
            for (int mi = 0; mi < 4; mi++)
                #pragma unroll
                for (int ni = 0; ni < 4; ni++)
                    mma_fp16(acc[mi][ni], a[mi], &b[ni >> 1][(ni & 1) * 2]);
        }
        __syncthreads();
    }

    // fused cosine epilogue
    const int rbase = row0 + wm * 64 + (lane >> 2);
    const int cbase = col0 + wn * 32 + (lane & 3) * 2;
    #pragma unroll
    for (int mi = 0; mi < 4; mi++) {
        const int r = rbase + mi * 16;
        const float n0 = g_rnx[r];
        const float n1 = g_rnx[r + 8];
        #pragma unroll
        for (int ni = 0; ni < 4; ni++) {
            const int c = cbase + ni * 8;
            const float2 ry = *reinterpret_cast<const float2*>(g_rny + c);
            float2 o0, o1;
            o0.x = acc[mi][ni][0] * n0 * ry.x;
            o0.y = acc[mi][ni][1] * n0 * ry.y;
            o1.x = acc[mi][ni][2] * n1 * ry.x;
            o1.y = acc[mi][ni][3] * n1 * ry.y;
            *reinterpret_cast<float2*>(O + (size_t)r * NROW + c)       = o0;
            *reinterpret_cast<float2*>(O + (size_t)(r + 8) * NROW + c) = o1;
        }
    }
}

extern "C" void kernel_launch(void* const* d_in, const int* in_sizes, int n_in,
                              void* d_out, int out_size) {
    const float* x = (const float*)d_in[0];
    const float* y = (const float*)d_in[1];
    float* o = (float*)d_out;
    (void)in_sizes; (void)n_in; (void)out_size;

    prep_kernel<<<2 * NROW, 256>>>(x, y);

    cudaFuncSetAttribute(cosgemm_kernel, cudaFuncAttributeMaxDynamicSharedMemorySize, SMEM_TOTAL);
    cosgemm_kernel<<<dim3(NROW / BN, NROW / BM), 256, SMEM_TOTAL>>>(o);
}

// round 5
// speedup vs baseline: 8.3535x; 1.1206x over previous
#include <cuda_runtime.h>
#include <cuda_fp16.h>
#include <cstdint>

#define D       1024
#define NROW    4096
#define BM      128
#define BN      128
#define BK      64                 // 64 fp16 = 128 B per row-chunk
#define NCHUNK  (D / BK)           // 16
#define ROWB    128                // bytes per smem row (XOR-swizzled)
#define ARRB    (128 * ROWB)       // 16 KB per operand per stage
#define STAGEB  (2 * ARRB)         // 32 KB
#define NSTAGE  3
#define SMEM_TOTAL (NSTAGE * STAGEB)   // 98304 B -> 2 CTAs/SM

// ---- scratch (allocation-guard-safe __device__ globals) ----
__device__ __align__(256) __half g_xh[NROW * D];
__device__ __align__(256) __half g_yh[NROW * D];
__device__ __align__(16)  float  g_rnx[NROW];   // 20 / ||x_i||  (temp folded)
__device__ __align__(16)  float  g_rny[NROW];   // 1 / ||y_j||

// ---- helpers ----
__device__ __forceinline__ uint32_t smem_u32(const void* p) {
    uint32_t a;
    asm("{ .reg .u64 t; cvta.to.shared.u64 t, %1; cvt.u32.u64 %0, t; }" : "=r"(a) : "l"(p));
    return a;
}
__device__ __forceinline__ void cp16(uint32_t s, const void* g) {
    asm volatile("cp.async.cg.shared.global [%0], [%1], 16;" :: "r"(s), "l"(g));
}
#define CP_COMMIT() asm volatile("cp.async.commit_group;" ::: "memory")
template <int N>
__device__ __forceinline__ void cp_wait() {
    asm volatile("cp.async.wait_group %0;" :: "n"(N) : "memory");
}
__device__ __forceinline__ void ldsm4(uint32_t* r, uint32_t addr) {
    asm volatile("ldmatrix.sync.aligned.m8n8.x4.shared.b16 {%0,%1,%2,%3}, [%4];"
                 : "=r"(r[0]), "=r"(r[1]), "=r"(r[2]), "=r"(r[3]) : "r"(addr));
}
__device__ __forceinline__ void mma_fp16(float* d, const uint32_t* a, const uint32_t* b) {
    asm volatile(
        "mma.sync.aligned.m16n8k16.row.col.f32.f16.f16.f32 "
        "{%0,%1,%2,%3}, {%4,%5,%6,%7}, {%8,%9}, {%0,%1,%2,%3};"
        : "+f"(d[0]), "+f"(d[1]), "+f"(d[2]), "+f"(d[3])
        : "r"(a[0]), "r"(a[1]), "r"(a[2]), "r"(a[3]), "r"(b[0]), "r"(b[1]));
}

// ---- fused norm + fp16-convert prologue ----
__global__ __launch_bounds__(256) void prep_kernel(const float* __restrict__ x,
                                                   const float* __restrict__ y) {
    const int row = blockIdx.x;
    const bool isy = (row >= NROW);
    const int r = isy ? row - NROW : row;
    const float* p = (isy ? y : x) + (size_t)r * D;
    const float4 v = reinterpret_cast<const float4*>(p)[threadIdx.x];

    __half2 h0 = __floats2half2_rn(v.x, v.y);
    __half2 h1 = __floats2half2_rn(v.z, v.w);
    uint2 hv;
    hv.x = *reinterpret_cast<uint32_t*>(&h0);
    hv.y = *reinterpret_cast<uint32_t*>(&h1);
    reinterpret_cast<uint2*>((isy ? g_yh : g_xh) + (size_t)r * D)[threadIdx.x] = hv;

    float s = v.x * v.x + v.y * v.y + v.z * v.z + v.w * v.w;
    #pragma unroll
    for (int o = 16; o > 0; o >>= 1) s += __shfl_down_sync(0xffffffffu, s, o);
    __shared__ float ws[8];
    const int lane = threadIdx.x & 31, w = threadIdx.x >> 5;
    if (lane == 0) ws[w] = s;
    __syncthreads();
    if (threadIdx.x == 0) {
        float t = 0.f;
        #pragma unroll
        for (int i = 0; i < 8; i++) t += ws[i];
        const float n = sqrtf(t);
        if (isy) g_rny[r] = 1.0f / n;
        else     g_rnx[r] = 20.0f / n;
    }
}

// ---- main GEMM: fp16 mma.sync, fragment double-buffer, 1 barrier/chunk ----
__global__ __launch_bounds__(256, 2) void cosgemm_kernel(float* __restrict__ O) {
    extern __shared__ char smem[];
    const uint32_t sb = smem_u32(smem);
    const int tid = threadIdx.x;
    const int w = tid >> 5, lane = tid & 31;
    const int wm = w >> 2, wn = w & 3;      // 2 x 4 warp grid, warp tile 64x32
    const int row0 = blockIdx.y * BM;
    const int col0 = blockIdx.x * BN;
    const uint32_t lx = (uint32_t)(lane & 7);

    // cp.async slot 0; slots 1..3 are +4096 smem / +32*D gmem (uniform strides)
    const int r0 = tid >> 3, c0 = tid & 7;
    const uint32_t soff0 = (uint32_t)(r0 * ROWB + ((c0 ^ (r0 & 7)) * 16));
    const __half* pA = g_xh + (size_t)(row0 + r0) * D + c0 * 8;
    const __half* pB = g_yh + (size_t)(col0 + r0) * D + c0 * 8;

    // ldmatrix per-lane row bases
    const uint32_t arow = (uint32_t)((wm * 64 + (lane & 15)) * ROWB);
    const uint32_t brow = (uint32_t)((wn * 32 + (lane & 7) + ((lane >> 4) << 3)) * ROWB);
    const uint32_t acat = (uint32_t)(lane >> 4);
    const uint32_t bcat = (uint32_t)((lane >> 3) & 1);

    float acc[4][4][4];
    #pragma unroll
    for (int mi = 0; mi < 4; mi++)
        #pragma unroll
        for (int ni = 0; ni < 4; ni++)
            #pragma unroll
            for (int r = 0; r < 4; r++) acc[mi][ni][r] = 0.f;

    uint32_t afrag[2][4][4], bfrag[2][2][4];

#define LOAD_CHUNK(i) do {                                                      \
        const uint32_t st_ = sb + (uint32_t)((i) % NSTAGE) * STAGEB;            \
        const __half* a_ = pA + (i) * BK;                                       \
        const __half* b_ = pB + (i) * BK;                                       \
        _Pragma("unroll")                                                       \
        for (int k_ = 0; k_ < 4; k_++)                                          \
            cp16(st_ + soff0 + 4096u * k_, a_ + (size_t)(32 * k_) * D);         \
        _Pragma("unroll")                                                       \
        for (int k_ = 0; k_ < 4; k_++)                                          \
            cp16(st_ + ARRB + soff0 + 4096u * k_, b_ + (size_t)(32 * k_) * D);  \
        CP_COMMIT();                                                            \
    } while (0)

#define LDSM_STEP(st_, s_, buf_) do {                                           \
        const uint32_t aco_ = (((uint32_t)(s_) * 2 + acat) ^ lx) * 16;          \
        const uint32_t bco_ = (((uint32_t)(s_) * 2 + bcat) ^ lx) * 16;          \
        _Pragma("unroll")                                                       \
        for (int mi_ = 0; mi_ < 4; mi_++)                                       \
            ldsm4(afrag[buf_][mi_], (st_) + arow + (uint32_t)(mi_ * 16 * ROWB) + aco_); \
        _Pragma("unroll")                                                       \
        for (int np_ = 0; np_ < 2; np_++)                                       \
            ldsm4(bfrag[buf_][np_], (st_) + ARRB + brow + (uint32_t)(np_ * 16 * ROWB) + bco_); \
    } while (0)

    LOAD_CHUNK(0);
    LOAD_CHUNK(1);
    LOAD_CHUNK(2);
    cp_wait<2>();
    __syncthreads();
    LDSM_STEP(sb, 0, 0);     // chunk 0, k-step 0 -> buffer 0

    #pragma unroll
    for (int i = 0; i < NCHUNK; i++) {
        const uint32_t st = sb + (uint32_t)(i % NSTAGE) * STAGEB;

        #pragma unroll
        for (int s = 0; s < 4; s++) {
            const int cur = s & 1;
            if (s < 3) LDSM_STEP(st, s + 1, cur ^ 1);   // prefetch next k-step
            #pragma unroll
            for (int mi = 0; mi < 4; mi++)
                #pragma unroll
                for (int ni = 0; ni < 4; ni++)
                    mma_fp16(acc[mi][ni], afrag[cur][mi],
                             &bfrag[cur][ni >> 1][(ni & 1) * 2]);
        }

        if (i == NCHUNK - 1) break;

        // make stage i+1 visible, recycle stage i, prefetch next chunk step 0
        if (i + 3 < NCHUNK) {
            cp_wait<1>();
            __syncthreads();
            LOAD_CHUNK(i + 3);
        } else if (i == NCHUNK - 3) {
            cp_wait<1>();
            __syncthreads();
        } else {                 // i == NCHUNK - 2
            cp_wait<0>();
            __syncthreads();
        }
        LDSM_STEP(sb + (uint32_t)((i + 1) % NSTAGE) * STAGEB, 0, 0);
    }

    // fused cosine epilogue
    const int rbase = row0 + wm * 64 + (lane >> 2);
    const int cbase = col0 + wn * 32 + (lane & 3) * 2;
    #pragma unroll
    for (int mi = 0; mi < 4; mi++) {
        const int r = rbase + mi * 16;
        const float n0 = g_rnx[r];
        const float n1 = g_rnx[r + 8];
        #pragma unroll
        for (int ni = 0; ni < 4; ni++) {
            const int c = cbase + ni * 8;
            const float2 ry = *reinterpret_cast<const float2*>(g_rny + c);
            float2 o0, o1;
            o0.x = acc[mi][ni][0] * n0 * ry.x;
            o0.y = acc[mi][ni][1] * n0 * ry.y;
            o1.x = acc[mi][ni][2] * n1 * ry.x;
            o1.y = acc[mi][ni][3] * n1 * ry.y;
            *reinterpret_cast<float2*>(O + (size_t)r * NROW + c)       = o0;
            *reinterpret_cast<float2*>(O + (size_t)(r + 8) * NROW + c) = o1;
        }
    }
}

extern "C" void kernel_launch(void* const* d_in, const int* in_sizes, int n_in,
                              void* d_out, int out_size) {
    const float* x = (const float*)d_in[0];
    const float* y = (const float*)d_in[1];
    float* o = (float*)d_out;
    (void)in_sizes; (void)n_in; (void)out_size;

    prep_kernel<<<2 * NROW, 256>>>(x, y);

    cudaFuncSetAttribute(cosgemm_kernel, cudaFuncAttributeMaxDynamicSharedMemorySize, SMEM_TOTAL);
    cosgemm_kernel<<<dim3(NROW / BN, NROW / BM), 256, SMEM_TOTAL>>>(o);
}

// round 6
// speedup vs baseline: 8.4496x; 1.0115x over previous
#include <cuda_runtime.h>
#include <cuda_fp16.h>
#include <cstdint>

#define D       1024
#define NROW    4096
#define BM      128
#define BN      128
#define BK      64                 // 64 fp16 = 128 B per row-chunk
#define NCHUNK  (D / BK)           // 16
#define ROWB    128                // bytes per smem row (XOR-swizzled)
#define ARRB    (128 * ROWB)       // 16 KB per operand per stage
#define STAGEB  (2 * ARRB)         // 32 KB
#define NSTAGE  3
#define SMEM_TOTAL (NSTAGE * STAGEB)   // 98304 B -> 2 CTAs/SM

// ---- scratch (allocation-guard-safe __device__ globals) ----
__device__ __align__(256) __half g_xh[NROW * D];
__device__ __align__(256) __half g_yh[NROW * D];
__device__ __align__(16)  float  g_rnx[NROW];   // 20 / ||x_i||  (temp folded)
__device__ __align__(16)  float  g_rny[NROW];   // 1 / ||y_j||

// ---- helpers ----
__device__ __forceinline__ uint32_t smem_u32(const void* p) {
    uint32_t a;
    asm("{ .reg .u64 t; cvta.to.shared.u64 t, %1; cvt.u32.u64 %0, t; }" : "=r"(a) : "l"(p));
    return a;
}
__device__ __forceinline__ void cp16(uint32_t s, const void* g) {
    asm volatile("cp.async.cg.shared.global [%0], [%1], 16;" :: "r"(s), "l"(g));
}
#define CP_COMMIT() asm volatile("cp.async.commit_group;" ::: "memory")
template <int N>
__device__ __forceinline__ void cp_wait() {
    asm volatile("cp.async.wait_group %0;" :: "n"(N) : "memory");
}
__device__ __forceinline__ void ldsm4(uint32_t* r, uint32_t addr) {
    asm volatile("ldmatrix.sync.aligned.m8n8.x4.shared.b16 {%0,%1,%2,%3}, [%4];"
                 : "=r"(r[0]), "=r"(r[1]), "=r"(r[2]), "=r"(r[3]) : "r"(addr));
}
__device__ __forceinline__ void mma_fp16(float* d, const uint32_t* a, const uint32_t* b) {
    asm volatile(
        "mma.sync.aligned.m16n8k16.row.col.f32.f16.f16.f32 "
        "{%0,%1,%2,%3}, {%4,%5,%6,%7}, {%8,%9}, {%0,%1,%2,%3};"
        : "+f"(d[0]), "+f"(d[1]), "+f"(d[2]), "+f"(d[3])
        : "r"(a[0]), "r"(a[1]), "r"(a[2]), "r"(a[3]), "r"(b[0]), "r"(b[1]));
}

// ---- prep: warp-per-row, deep-MLP loads, shuffle-only norm reduction ----
__global__ __launch_bounds__(256) void prep_kernel(const float* __restrict__ x,
                                                   const float* __restrict__ y) {
    const int wid = blockIdx.x * 8 + (threadIdx.x >> 5);   // global row 0..8191
    const int lane = threadIdx.x & 31;
    const bool isy = (wid >= NROW);
    const int r = isy ? wid - NROW : wid;
    const float4* p4 = reinterpret_cast<const float4*>((isy ? y : x) + (size_t)r * D);
    uint2* dst = reinterpret_cast<uint2*>((isy ? g_yh : g_xh) + (size_t)r * D);

    float4 v[8];
    #pragma unroll
    for (int j = 0; j < 8; j++) v[j] = p4[lane + 32 * j];   // 8-deep MLP

    float s = 0.f;
    #pragma unroll
    for (int j = 0; j < 8; j++) {
        s += v[j].x * v[j].x + v[j].y * v[j].y + v[j].z * v[j].z + v[j].w * v[j].w;
        __half2 h0 = __floats2half2_rn(v[j].x, v[j].y);
        __half2 h1 = __floats2half2_rn(v[j].z, v[j].w);
        uint2 hv;
        hv.x = *reinterpret_cast<uint32_t*>(&h0);
        hv.y = *reinterpret_cast<uint32_t*>(&h1);
        dst[lane + 32 * j] = hv;
    }
    #pragma unroll
    for (int o = 16; o > 0; o >>= 1) s += __shfl_down_sync(0xffffffffu, s, o);
    if (lane == 0) {
        const float n = sqrtf(s);
        if (isy) g_rny[r] = 1.0f / n;
        else     g_rnx[r] = 20.0f / n;
    }
}

// ---- main GEMM: fp16 mma.sync, barrier hidden behind last k-step MMAs ----
__global__ __launch_bounds__(256, 2) void cosgemm_kernel(float* __restrict__ O) {
    extern __shared__ char smem[];
    const uint32_t sb = smem_u32(smem);
    const int tid = threadIdx.x;
    const int w = tid >> 5, lane = tid & 31;
    const int wm = w >> 2, wn = w & 3;      // 2 x 4 warp grid, warp tile 64x32
    const int row0 = blockIdx.y * BM;
    const int col0 = blockIdx.x * BN;
    const uint32_t lx = (uint32_t)(lane & 7);

    const int r0 = tid >> 3, c0 = tid & 7;
    const uint32_t soff0 = (uint32_t)(r0 * ROWB + ((c0 ^ (r0 & 7)) * 16));
    const __half* pA = g_xh + (size_t)(row0 + r0) * D + c0 * 8;
    const __half* pB = g_yh + (size_t)(col0 + r0) * D + c0 * 8;

    const uint32_t arow = (uint32_t)((wm * 64 + (lane & 15)) * ROWB);
    const uint32_t brow = (uint32_t)((wn * 32 + (lane & 7) + ((lane >> 4) << 3)) * ROWB);
    const uint32_t acat = (uint32_t)(lane >> 4);
    const uint32_t bcat = (uint32_t)((lane >> 3) & 1);

    float acc[4][4][4];
    #pragma unroll
    for (int mi = 0; mi < 4; mi++)
        #pragma unroll
        for (int ni = 0; ni < 4; ni++)
            #pragma unroll
            for (int r = 0; r < 4; r++) acc[mi][ni][r] = 0.f;

    uint32_t afrag[2][4][4], bfrag[2][2][4];

#define LOAD_CHUNK(i) do {                                                      \
        const uint32_t st_ = sb + (uint32_t)((i) % NSTAGE) * STAGEB;            \
        const __half* a_ = pA + (i) * BK;                                       \
        const __half* b_ = pB + (i) * BK;                                       \
        _Pragma("unroll")                                                       \
        for (int k_ = 0; k_ < 4; k_++)                                          \
            cp16(st_ + soff0 + 4096u * k_, a_ + (size_t)(32 * k_) * D);         \
        _Pragma("unroll")                                                       \
        for (int k_ = 0; k_ < 4; k_++)                                          \
            cp16(st_ + ARRB + soff0 + 4096u * k_, b_ + (size_t)(32 * k_) * D);  \
        CP_COMMIT();                                                            \
    } while (0)

#define LDSM_STEP(st_, s_, buf_) do {                                           \
        const uint32_t aco_ = (((uint32_t)(s_) * 2 + acat) ^ lx) * 16;          \
        const uint32_t bco_ = (((uint32_t)(s_) * 2 + bcat) ^ lx) * 16;          \
        _Pragma("unroll")                                                       \
        for (int mi_ = 0; mi_ < 4; mi_++)                                       \
            ldsm4(afrag[buf_][mi_], (st_) + arow + (uint32_t)(mi_ * 16 * ROWB) + aco_); \
        _Pragma("unroll")                                                       \
        for (int np_ = 0; np_ < 2; np_++)                                       \
            ldsm4(bfrag[buf_][np_], (st_) + ARRB + brow + (uint32_t)(np_ * 16 * ROWB) + bco_); \
    } while (0)

#define MMA_ALL(buf_) do {                                                      \
        _Pragma("unroll")                                                       \
        for (int mi_ = 0; mi_ < 4; mi_++)                                       \
            _Pragma("unroll")                                                   \
            for (int ni_ = 0; ni_ < 4; ni_++)                                   \
                mma_fp16(acc[mi_][ni_], afrag[buf_][mi_],                       \
                         &bfrag[buf_][ni_ >> 1][(ni_ & 1) * 2]);                \
    } while (0)

    LOAD_CHUNK(0);
    LOAD_CHUNK(1);
    LOAD_CHUNK(2);
    cp_wait<2>();
    __syncthreads();
    LDSM_STEP(sb, 0, 0);     // chunk 0, k-step 0 -> buffer 0

    #pragma unroll
    for (int i = 0; i < NCHUNK; i++) {
        const uint32_t st = sb + (uint32_t)(i % NSTAGE) * STAGEB;

        // k-steps 0..2; each prefetches the next step's fragments
        #pragma unroll
        for (int s = 0; s < 3; s++) {
            LDSM_STEP(st, s + 1, (s & 1) ^ 1);
            MMA_ALL(s & 1);
        }

        // All reads of stage i are complete (step-3 frags in regs).
        // Hide barrier + next-chunk LDSM behind the s=3 MMAs below.
        if (i < NCHUNK - 1) {
            if (i + 3 < NCHUNK) {
                cp_wait<1>();
                __syncthreads();
                LOAD_CHUNK(i + 3);
            } else if (i == NCHUNK - 3) {
                cp_wait<1>();
                __syncthreads();
            } else {             // i == NCHUNK - 2
                cp_wait<0>();
                __syncthreads();
            }
            LDSM_STEP(sb + (uint32_t)((i + 1) % NSTAGE) * STAGEB, 0, 0);
        }

        MMA_ALL(1);              // k-step 3
    }

    // fused cosine epilogue
    const int rbase = row0 + wm * 64 + (lane >> 2);
    const int cbase = col0 + wn * 32 + (lane & 3) * 2;
    #pragma unroll
    for (int mi = 0; mi < 4; mi++) {
        const int r = rbase + mi * 16;
        const float n0 = g_rnx[r];
        const float n1 = g_rnx[r + 8];
        #pragma unroll
        for (int ni = 0; ni < 4; ni++) {
            const int c = cbase + ni * 8;
            const float2 ry = *reinterpret_cast<const float2*>(g_rny + c);
            float2 o0, o1;
            o0.x = acc[mi][ni][0] * n0 * ry.x;
            o0.y = acc[mi][ni][1] * n0 * ry.y;
            o1.x = acc[mi][ni][2] * n1 * ry.x;
            o1.y = acc[mi][ni][3] * n1 * ry.y;
            *reinterpret_cast<float2*>(O + (size_t)r * NROW + c)       = o0;
            *reinterpret_cast<float2*>(O + (size_t)(r + 8) * NROW + c) = o1;
        }
    }
}

extern "C" void kernel_launch(void* const* d_in, const int* in_sizes, int n_in,
                              void* d_out, int out_size) {
    const float* x = (const float*)d_in[0];
    const float* y = (const float*)d_in[1];
    float* o = (float*)d_out;
    (void)in_sizes; (void)n_in; (void)out_size;

    prep_kernel<<<(2 * NROW) / 8, 256>>>(x, y);

    cudaFuncSetAttribute(cosgemm_kernel, cudaFuncAttributeMaxDynamicSharedMemorySize, SMEM_TOTAL);
    cosgemm_kernel<<<dim3(NROW / BN, NROW / BM), 256, SMEM_TOTAL>>>(o);
}

// round 7
// speedup vs baseline: 8.5294x; 1.0094x over previous
#include <cuda_runtime.h>
#include <cuda_fp16.h>
#include <cstdint>

#define D       1024
#define NROW    4096
#define BM      128
#define BN      128
#define BK      64                 // 64 fp16 = 128 B per row-chunk
#define NCHUNK  (D / BK)           // 16
#define ROWB    128                // bytes per smem row (XOR-swizzled)
#define ARRB    (128 * ROWB)       // 16 KB per operand per stage
#define STAGEB  (2 * ARRB)         // 32 KB
#define NSTAGE  3
#define SMEM_TOTAL (NSTAGE * STAGEB)   // 98304 B -> 2 CTAs/SM

// ---- scratch (allocation-guard-safe __device__ globals) ----
__device__ __align__(256) __half g_xh[NROW * D];
__device__ __align__(256) __half g_yh[NROW * D];
__device__ __align__(16)  float  g_rnx[NROW];   // 20 / ||x_i||  (temp folded)
__device__ __align__(16)  float  g_rny[NROW];   // 1 / ||y_j||

// ---- helpers ----
__device__ __forceinline__ uint32_t smem_u32(const void* p) {
    uint32_t a;
    asm("{ .reg .u64 t; cvta.to.shared.u64 t, %1; cvt.u32.u64 %0, t; }" : "=r"(a) : "l"(p));
    return a;
}
__device__ __forceinline__ void cp16(uint32_t s, const void* g) {
    asm volatile("cp.async.cg.shared.global [%0], [%1], 16;" :: "r"(s), "l"(g));
}
#define CP_COMMIT() asm volatile("cp.async.commit_group;" ::: "memory")
template <int N>
__device__ __forceinline__ void cp_wait() {
    asm volatile("cp.async.wait_group %0;" :: "n"(N) : "memory");
}
__device__ __forceinline__ void ldsm4(uint32_t* r, uint32_t addr) {
    asm volatile("ldmatrix.sync.aligned.m8n8.x4.shared.b16 {%0,%1,%2,%3}, [%4];"
                 : "=r"(r[0]), "=r"(r[1]), "=r"(r[2]), "=r"(r[3]) : "r"(addr));
}
__device__ __forceinline__ void mma_fp16(float* d, const uint32_t* a, const uint32_t* b) {
    asm volatile(
        "mma.sync.aligned.m16n8k16.row.col.f32.f16.f16.f32 "
        "{%0,%1,%2,%3}, {%4,%5,%6,%7}, {%8,%9}, {%0,%1,%2,%3};"
        : "+f"(d[0]), "+f"(d[1]), "+f"(d[2]), "+f"(d[3])
        : "r"(a[0]), "r"(a[1]), "r"(a[2]), "r"(a[3]), "r"(b[0]), "r"(b[1]));
}

// ---- prep: warp-per-row, coalesced loads, smem-staged 16B stores ----
__global__ __launch_bounds__(256) void prep_kernel(const float* __restrict__ x,
                                                   const float* __restrict__ y) {
    __shared__ uint2 stage[8][256];          // 2 KB per warp
    const int w = threadIdx.x >> 5;
    const int lane = threadIdx.x & 31;
    const int wid = blockIdx.x * 8 + w;      // global row 0..8191
    const bool isy = (wid >= NROW);
    const int r = isy ? wid - NROW : wid;
    const float4* p4 = reinterpret_cast<const float4*>((isy ? y : x) + (size_t)r * D);
    uint4* dst = reinterpret_cast<uint4*>((isy ? g_yh : g_xh) + (size_t)r * D);

    float4 v[8];
    #pragma unroll
    for (int j = 0; j < 8; j++) v[j] = p4[lane + 32 * j];   // coalesced, 8-deep MLP

    float s = 0.f;
    #pragma unroll
    for (int j = 0; j < 8; j++) {
        s += v[j].x * v[j].x + v[j].y * v[j].y + v[j].z * v[j].z + v[j].w * v[j].w;
        __half2 h0 = __floats2half2_rn(v[j].x, v[j].y);
        __half2 h1 = __floats2half2_rn(v[j].z, v[j].w);
        uint2 hv;
        hv.x = *reinterpret_cast<uint32_t*>(&h0);
        hv.y = *reinterpret_cast<uint32_t*>(&h1);
        stage[w][lane + 32 * j] = hv;        // stage[w][i] = halves 4i..4i+3
    }
    __syncwarp();

    // lane emits uint4 k for k in {lane, lane+32, lane+64, lane+96}: coalesced STG.128
    #pragma unroll
    for (int t = 0; t < 4; t++) {
        const int k = lane + 32 * t;
        const uint2 a = stage[w][2 * k];
        const uint2 b = stage[w][2 * k + 1];
        dst[k] = make_uint4(a.x, a.y, b.x, b.y);
    }

    #pragma unroll
    for (int o = 16; o > 0; o >>= 1) s += __shfl_down_sync(0xffffffffu, s, o);
    if (lane == 0) {
        const float n = sqrtf(s);
        if (isy) g_rny[r] = 1.0f / n;
        else     g_rnx[r] = 20.0f / n;
    }
}

// ---- main GEMM: fp16 mma.sync, fragment double-buffer (unchanged core) ----
__global__ __launch_bounds__(256, 2) void cosgemm_kernel(float* __restrict__ O) {
    extern __shared__ char smem[];
    const uint32_t sb = smem_u32(smem);
    const int tid = threadIdx.x;
    const int w = tid >> 5, lane = tid & 31;
    const int wm = w >> 2, wn = w & 3;      // 2 x 4 warp grid, warp tile 64x32
    const int row0 = blockIdx.y * BM;
    const int col0 = blockIdx.x * BN;
    const uint32_t lx = (uint32_t)(lane & 7);

    const int r0 = tid >> 3, c0 = tid & 7;
    const uint32_t soff0 = (uint32_t)(r0 * ROWB + ((c0 ^ (r0 & 7)) * 16));
    const __half* pA = g_xh + (size_t)(row0 + r0) * D + c0 * 8;
    const __half* pB = g_yh + (size_t)(col0 + r0) * D + c0 * 8;

    const uint32_t arow = (uint32_t)((wm * 64 + (lane & 15)) * ROWB);
    const uint32_t brow = (uint32_t)((wn * 32 + (lane & 7) + ((lane >> 4) << 3)) * ROWB);
    const uint32_t acat = (uint32_t)(lane >> 4);
    const uint32_t bcat = (uint32_t)((lane >> 3) & 1);

    float acc[4][4][4];
    #pragma unroll
    for (int mi = 0; mi < 4; mi++)
        #pragma unroll
        for (int ni = 0; ni < 4; ni++)
            #pragma unroll
            for (int r = 0; r < 4; r++) acc[mi][ni][r] = 0.f;

    uint32_t afrag[2][4][4], bfrag[2][2][4];

#define LOAD_CHUNK(i) do {                                                      \
        const uint32_t st_ = sb + (uint32_t)((i) % NSTAGE) * STAGEB;            \
        const __half* a_ = pA + (i) * BK;                                       \
        const __half* b_ = pB + (i) * BK;                                       \
        _Pragma("unroll")                                                       \
        for (int k_ = 0; k_ < 4; k_++)                                          \
            cp16(st_ + soff0 + 4096u * k_, a_ + (size_t)(32 * k_) * D);         \
        _Pragma("unroll")                                                       \
        for (int k_ = 0; k_ < 4; k_++)                                          \
            cp16(st_ + ARRB + soff0 + 4096u * k_, b_ + (size_t)(32 * k_) * D);  \
        CP_COMMIT();                                                            \
    } while (0)

#define LDSM_STEP(st_, s_, buf_) do {                                           \
        const uint32_t aco_ = (((uint32_t)(s_) * 2 + acat) ^ lx) * 16;          \
        const uint32_t bco_ = (((uint32_t)(s_) * 2 + bcat) ^ lx) * 16;          \
        _Pragma("unroll")                                                       \
        for (int mi_ = 0; mi_ < 4; mi_++)                                       \
            ldsm4(afrag[buf_][mi_], (st_) + arow + (uint32_t)(mi_ * 16 * ROWB) + aco_); \
        _Pragma("unroll")                                                       \
        for (int np_ = 0; np_ < 2; np_++)                                       \
            ldsm4(bfrag[buf_][np_], (st_) + ARRB + brow + (uint32_t)(np_ * 16 * ROWB) + bco_); \
    } while (0)

#define MMA_ALL(buf_) do {                                                      \
        _Pragma("unroll")                                                       \
        for (int mi_ = 0; mi_ < 4; mi_++)                                       \
            _Pragma("unroll")                                                   \
            for (int ni_ = 0; ni_ < 4; ni_++)                                   \
                mma_fp16(acc[mi_][ni_], afrag[buf_][mi_],                       \
                         &bfrag[buf_][ni_ >> 1][(ni_ & 1) * 2]);                \
    } while (0)

    LOAD_CHUNK(0);
    LOAD_CHUNK(1);
    LOAD_CHUNK(2);
    cp_wait<2>();
    __syncthreads();
    LDSM_STEP(sb, 0, 0);     // chunk 0, k-step 0 -> buffer 0

    #pragma unroll
    for (int i = 0; i < NCHUNK; i++) {
        const uint32_t st = sb + (uint32_t)(i % NSTAGE) * STAGEB;

        #pragma unroll
        for (int s = 0; s < 3; s++) {
            LDSM_STEP(st, s + 1, (s & 1) ^ 1);
            MMA_ALL(s & 1);
        }

        if (i < NCHUNK - 1) {
            if (i + 3 < NCHUNK) {
                cp_wait<1>();
                __syncthreads();
                LOAD_CHUNK(i + 3);
            } else if (i == NCHUNK - 3) {
                cp_wait<1>();
                __syncthreads();
            } else {             // i == NCHUNK - 2
                cp_wait<0>();
                __syncthreads();
            }
            LDSM_STEP(sb + (uint32_t)((i + 1) % NSTAGE) * STAGEB, 0, 0);
        }

        MMA_ALL(1);              // k-step 3
    }

    // fused cosine epilogue
    const int rbase = row0 + wm * 64 + (lane >> 2);
    const int cbase = col0 + wn * 32 + (lane & 3) * 2;
    #pragma unroll
    for (int mi = 0; mi < 4; mi++) {
        const int r = rbase + mi * 16;
        const float n0 = __ldg(g_rnx + r);
        const float n1 = __ldg(g_rnx + r + 8);
        #pragma unroll
        for (int ni = 0; ni < 4; ni++) {
            const int c = cbase + ni * 8;
            const float2 ry = __ldg(reinterpret_cast<const float2*>(g_rny + c));
            float2 o0, o1;
            o0.x = acc[mi][ni][0] * n0 * ry.x;
            o0.y = acc[mi][ni][1] * n0 * ry.y;
            o1.x = acc[mi][ni][2] * n1 * ry.x;
            o1.y = acc[mi][ni][3] * n1 * ry.y;
            *reinterpret_cast<float2*>(O + (size_t)r * NROW + c)       = o0;
            *reinterpret_cast<float2*>(O + (size_t)(r + 8) * NROW + c) = o1;
        }
    }
}

extern "C" void kernel_launch(void* const* d_in, const int* in_sizes, int n_in,
                              void* d_out, int out_size) {
    const float* x = (const float*)d_in[0];
    const float* y = (const float*)d_in[1];
    float* o = (float*)d_out;
    (void)in_sizes; (void)n_in; (void)out_size;

    prep_kernel<<<(2 * NROW) / 8, 256>>>(x, y);

    cudaFuncSetAttribute(cosgemm_kernel, cudaFuncAttributeMaxDynamicSharedMemorySize, SMEM_TOTAL);
    cosgemm_kernel<<<dim3(NROW / BN, NROW / BM), 256, SMEM_TOTAL>>>(o);
}